// round 1
// baseline (speedup 1.0000x reference)
#include <cuda_runtime.h>
#include <math.h>

// Problem constants
#define BSZ 4
#define SEQ 2048
#define CH  768
#define NH  12
#define HD  64
#define TOK (BSZ*SEQ)   // 8192
#define C3  (3*CH)      // 2304
#define BH  (BSZ*NH)    // 48

// Scratch (allocation-free per harness rules)
__device__ float g_xn[TOK*CH];
__device__ float g_q[BH*SEQ*HD];
__device__ float g_k[BH*SEQ*HD];
__device__ float g_v[BH*SEQ*HD];
__device__ float g_att[TOK*CH];

// ---------------------------------------------------------------------------
// 1) LayerNorm: one block per token, 256 threads, 3 elems/thread
// ---------------------------------------------------------------------------
__global__ void ln_kernel(const float* __restrict__ x,
                          const float* __restrict__ gamma,
                          const float* __restrict__ beta) {
    int t = blockIdx.x;
    const float* xr = x + (size_t)t * CH;
    int i0 = threadIdx.x, i1 = i0 + 256, i2 = i0 + 512;
    float v0 = xr[i0], v1 = xr[i1], v2 = xr[i2];
    float s  = v0 + v1 + v2;
    float s2 = v0*v0 + v1*v1 + v2*v2;
    #pragma unroll
    for (int o = 16; o > 0; o >>= 1) {
        s  += __shfl_down_sync(0xffffffffu, s,  o);
        s2 += __shfl_down_sync(0xffffffffu, s2, o);
    }
    __shared__ float ws[8], ws2[8];
    __shared__ float mu_s, inv_s;
    int w = threadIdx.x >> 5, l = threadIdx.x & 31;
    if (l == 0) { ws[w] = s; ws2[w] = s2; }
    __syncthreads();
    if (threadIdx.x == 0) {
        float a = 0.f, b = 0.f;
        #pragma unroll
        for (int k = 0; k < 8; k++) { a += ws[k]; b += ws2[k]; }
        float mu  = a * (1.0f / CH);
        float var = b * (1.0f / CH) - mu * mu;
        mu_s  = mu;
        inv_s = rsqrtf(var + 1e-5f);
    }
    __syncthreads();
    float mu = mu_s, inv = inv_s;
    float* orow = g_xn + (size_t)t * CH;
    orow[i0] = (v0 - mu) * inv * gamma[i0] + beta[i0];
    orow[i1] = (v1 - mu) * inv * gamma[i1] + beta[i1];
    orow[i2] = (v2 - mu) * inv * gamma[i2] + beta[i2];
}

// ---------------------------------------------------------------------------
// 2) QKV GEMM: g_xn[8192,768] @ w_qkv[768,2304], epilogue scatters to
//    head-major Q/K/V [BH, SEQ, HD]. Tiles 64x64x16, 4x4 per thread.
// ---------------------------------------------------------------------------
__global__ void gemm_qkv_kernel(const float* __restrict__ W) {
    __shared__ float As[16][64];   // A^T: [k][m]
    __shared__ float Bs[16][64];   // [k][n]
    int tid = threadIdx.x;
    int tx = tid & 15, ty = tid >> 4;
    int m0 = blockIdx.y * 64;
    int n0 = blockIdx.x * 64;
    float acc[4][4] = {};
    int ar = tid >> 2;        // 0..63  (A tile row = m)
    int ac = (tid & 3) * 4;   // 0,4,8,12 (A tile col = k)
    int bk = tid >> 4;        // 0..15
    int bn = (tid & 15) * 4;  // 0..60

    for (int k0 = 0; k0 < CH; k0 += 16) {
        float4 av = *(const float4*)&g_xn[(size_t)(m0 + ar) * CH + k0 + ac];
        As[ac + 0][ar] = av.x; As[ac + 1][ar] = av.y;
        As[ac + 2][ar] = av.z; As[ac + 3][ar] = av.w;
        *(float4*)&Bs[bk][bn] = *(const float4*)&W[(size_t)(k0 + bk) * C3 + n0 + bn];
        __syncthreads();
        #pragma unroll
        for (int kc = 0; kc < 16; kc++) {
            float4 a = *(float4*)&As[kc][ty * 4];
            float4 b = *(float4*)&Bs[kc][tx * 4];
            float aa[4] = {a.x, a.y, a.z, a.w};
            float bb[4] = {b.x, b.y, b.z, b.w};
            #pragma unroll
            for (int i = 0; i < 4; i++)
                #pragma unroll
                for (int j = 0; j < 4; j++)
                    acc[i][j] += aa[i] * bb[j];
        }
        __syncthreads();
    }
    // Epilogue: which of q/k/v, which head (constant across the 64-wide tile)
    int which = n0 / CH;
    int h     = (n0 % CH) >> 6;
    int dbase = tx * 4;
    float* dst = (which == 0) ? g_q : ((which == 1) ? g_k : g_v);
    #pragma unroll
    for (int i = 0; i < 4; i++) {
        int m = m0 + ty * 4 + i;
        int b = m >> 11;        // / SEQ
        int n = m & (SEQ - 1);
        float4 v = make_float4(acc[i][0], acc[i][1], acc[i][2], acc[i][3]);
        *(float4*)&dst[((size_t)(b * NH + h) * SEQ + n) * HD + dbase] = v;
    }
}

// ---------------------------------------------------------------------------
// 3) Flash attention: one block = 64 query rows of one (b,h).
//    Online softmax, shfl row reductions, K-smem buffer reused for P.
// ---------------------------------------------------------------------------
__global__ void attn_kernel() {
    __shared__ float QsT[64][64];  // [d][q]
    __shared__ float KPs[64][64];  // phase 1: K^T [d][kv]; phase 2: P [q][kv]
    __shared__ float Vs[64][64];   // [kv][d]

    int tid = threadIdx.x;
    int tx = tid & 15, ty = tid >> 4;
    int bh = blockIdx.y;
    int q0 = blockIdx.x * 64;
    const float scale = 0.125f;  // 1/sqrt(64)

    const float* Qg = g_q + (size_t)bh * SEQ * HD;
    const float* Kg = g_k + (size_t)bh * SEQ * HD;
    const float* Vg = g_v + (size_t)bh * SEQ * HD;

    int lr = tid >> 2;        // 0..63
    int lc = (tid & 3) * 16;  // 0,16,32,48

    // Load Q tile transposed + pre-scaled
    #pragma unroll
    for (int u = 0; u < 4; u++) {
        float4 v = *(const float4*)&Qg[(size_t)(q0 + lr) * HD + lc + u * 4];
        QsT[lc + u*4 + 0][lr] = v.x * scale;
        QsT[lc + u*4 + 1][lr] = v.y * scale;
        QsT[lc + u*4 + 2][lr] = v.z * scale;
        QsT[lc + u*4 + 3][lr] = v.w * scale;
    }

    float m_i[4], l_i[4], o[4][4];
    #pragma unroll
    for (int i = 0; i < 4; i++) {
        m_i[i] = -1e30f; l_i[i] = 0.f;
        #pragma unroll
        for (int j = 0; j < 4; j++) o[i][j] = 0.f;
    }

    for (int s0 = 0; s0 < SEQ; s0 += 64) {
        __syncthreads();  // previous iteration done reading KPs/Vs
        #pragma unroll
        for (int u = 0; u < 4; u++) {
            float4 kv = *(const float4*)&Kg[(size_t)(s0 + lr) * HD + lc + u * 4];
            KPs[lc + u*4 + 0][lr] = kv.x;
            KPs[lc + u*4 + 1][lr] = kv.y;
            KPs[lc + u*4 + 2][lr] = kv.z;
            KPs[lc + u*4 + 3][lr] = kv.w;
            float4 vv = *(const float4*)&Vg[(size_t)(s0 + lr) * HD + lc + u * 4];
            *(float4*)&Vs[lr][lc + u * 4] = vv;
        }
        __syncthreads();

        // S = Q K^T (scaled): 4x4 per thread, rows ty*4+i, cols tx*4+j
        float s[4][4] = {};
        #pragma unroll
        for (int d = 0; d < 64; d++) {
            float4 a = *(float4*)&QsT[d][ty * 4];
            float4 b = *(float4*)&KPs[d][tx * 4];
            float aa[4] = {a.x, a.y, a.z, a.w};
            float bb[4] = {b.x, b.y, b.z, b.w};
            #pragma unroll
            for (int i = 0; i < 4; i++)
                #pragma unroll
                for (int j = 0; j < 4; j++)
                    s[i][j] += aa[i] * bb[j];
        }

        // Online softmax. Row spread over 16 lanes (tx); shfl_xor 1..8 stays
        // in the 16-lane group since lane = (ty&1)*16 + tx.
        #pragma unroll
        for (int i = 0; i < 4; i++) {
            float mx = fmaxf(fmaxf(s[i][0], s[i][1]), fmaxf(s[i][2], s[i][3]));
            #pragma unroll
            for (int off = 8; off > 0; off >>= 1)
                mx = fmaxf(mx, __shfl_xor_sync(0xffffffffu, mx, off));
            float mnew = fmaxf(m_i[i], mx);
            float f = __expf(m_i[i] - mnew);
            float rs = 0.f;
            #pragma unroll
            for (int j = 0; j < 4; j++) {
                s[i][j] = __expf(s[i][j] - mnew);
                rs += s[i][j];
            }
            #pragma unroll
            for (int off = 8; off > 0; off >>= 1)
                rs += __shfl_xor_sync(0xffffffffu, rs, off);
            l_i[i] = l_i[i] * f + rs;
            m_i[i] = mnew;
            #pragma unroll
            for (int j = 0; j < 4; j++) o[i][j] *= f;
        }

        __syncthreads();  // done reading KPs as K
        // Write P row-major: P[q][kv]
        #pragma unroll
        for (int i = 0; i < 4; i++)
            #pragma unroll
            for (int j = 0; j < 4; j++)
                KPs[ty * 4 + i][tx * 4 + j] = s[i][j];
        __syncthreads();

        // O += P @ V  (kv tiled by 4 for vector loads)
        #pragma unroll
        for (int kk0 = 0; kk0 < 16; kk0++) {
            float4 bv[4];
            #pragma unroll
            for (int u = 0; u < 4; u++)
                bv[u] = *(float4*)&Vs[kk0 * 4 + u][tx * 4];
            #pragma unroll
            for (int i = 0; i < 4; i++) {
                float4 a = *(float4*)&KPs[ty * 4 + i][kk0 * 4];
                float aa[4] = {a.x, a.y, a.z, a.w};
                #pragma unroll
                for (int u = 0; u < 4; u++) {
                    float bb[4] = {bv[u].x, bv[u].y, bv[u].z, bv[u].w};
                    #pragma unroll
                    for (int j = 0; j < 4; j++)
                        o[i][j] += aa[u] * bb[j];
                }
            }
        }
    }

    // Epilogue: normalize, write token-major [B,N,C]
    int b = bh / NH, h = bh % NH;
    #pragma unroll
    for (int i = 0; i < 4; i++) {
        int r = q0 + ty * 4 + i;
        float invl = 1.0f / l_i[i];
        float4 v = make_float4(o[i][0]*invl, o[i][1]*invl, o[i][2]*invl, o[i][3]*invl);
        *(float4*)&g_att[((size_t)(b * SEQ + r)) * CH + h * HD + tx * 4] = v;
    }
}

// ---------------------------------------------------------------------------
// 4) Output GEMM + bias + residual: g_att[8192,768] @ w_out[768,768]
// ---------------------------------------------------------------------------
__global__ void gemm_out_kernel(const float* __restrict__ W,
                                const float* __restrict__ bias,
                                const float* __restrict__ resid,
                                float* __restrict__ out) {
    __shared__ float As[16][64];
    __shared__ float Bs[16][64];
    int tid = threadIdx.x;
    int tx = tid & 15, ty = tid >> 4;
    int m0 = blockIdx.y * 64;
    int n0 = blockIdx.x * 64;
    float acc[4][4] = {};
    int ar = tid >> 2;
    int ac = (tid & 3) * 4;
    int bk = tid >> 4;
    int bn = (tid & 15) * 4;

    for (int k0 = 0; k0 < CH; k0 += 16) {
        float4 av = *(const float4*)&g_att[(size_t)(m0 + ar) * CH + k0 + ac];
        As[ac + 0][ar] = av.x; As[ac + 1][ar] = av.y;
        As[ac + 2][ar] = av.z; As[ac + 3][ar] = av.w;
        *(float4*)&Bs[bk][bn] = *(const float4*)&W[(size_t)(k0 + bk) * CH + n0 + bn];
        __syncthreads();
        #pragma unroll
        for (int kc = 0; kc < 16; kc++) {
            float4 a = *(float4*)&As[kc][ty * 4];
            float4 b = *(float4*)&Bs[kc][tx * 4];
            float aa[4] = {a.x, a.y, a.z, a.w};
            float bb[4] = {b.x, b.y, b.z, b.w};
            #pragma unroll
            for (int i = 0; i < 4; i++)
                #pragma unroll
                for (int j = 0; j < 4; j++)
                    acc[i][j] += aa[i] * bb[j];
        }
        __syncthreads();
    }
    int n = n0 + tx * 4;
    float4 bv = *(const float4*)&bias[n];
    #pragma unroll
    for (int i = 0; i < 4; i++) {
        int m = m0 + ty * 4 + i;
        float4 rv = *(const float4*)&resid[(size_t)m * CH + n];
        float4 v = make_float4(acc[i][0] + bv.x + rv.x,
                               acc[i][1] + bv.y + rv.y,
                               acc[i][2] + bv.z + rv.z,
                               acc[i][3] + bv.w + rv.w);
        *(float4*)&out[(size_t)m * CH + n] = v;
    }
}

// ---------------------------------------------------------------------------
extern "C" void kernel_launch(void* const* d_in, const int* in_sizes, int n_in,
                              void* d_out, int out_size) {
    const float* img   = (const float*)d_in[0];
    const float* gamma = (const float*)d_in[1];
    const float* beta  = (const float*)d_in[2];
    const float* w_qkv = (const float*)d_in[3];
    const float* w_out = (const float*)d_in[4];
    const float* b_out = (const float*)d_in[5];
    float* out = (float*)d_out;

    ln_kernel<<<TOK, 256>>>(img, gamma, beta);
    gemm_qkv_kernel<<<dim3(C3 / 64, TOK / 64), 256>>>(w_qkv);
    attn_kernel<<<dim3(SEQ / 64, BH), 256>>>();
    gemm_out_kernel<<<dim3(CH / 64, TOK / 64), 256>>>(w_out, b_out, img, out);
}